// round 2
// baseline (speedup 1.0000x reference)
#include <cuda_runtime.h>
#include <math.h>

// Problem constants
#define BATCH 2
#define SEQ   2048
#define DMODEL 1024
#define NHEAD 16
#define DHEAD 64
#define MTOT  (BATCH*SEQ)      // 4096
#define LAMBDA_INIT 0.8f
#define LN_EPS 1e-5f

// ---------------------------------------------------------------------------
// Scratch (no allocation allowed -> __device__ globals)
// ---------------------------------------------------------------------------
__device__ float g_q0[MTOT*DMODEL];
__device__ float g_q1[MTOT*DMODEL];
__device__ float g_k0[MTOT*DMODEL];
__device__ float g_k1[MTOT*DMODEL];
__device__ float g_v [MTOT*DMODEL];
__device__ float g_attn[MTOT*DMODEL];
__device__ float g_lambda;

// ---------------------------------------------------------------------------
// Lambda scalar: lamb = (-exp(l0.l1)+0.8) + (-exp(l2.l3)+0.8)
// ---------------------------------------------------------------------------
__global__ void lambda_kernel(const float* __restrict__ l0, const float* __restrict__ l1,
                              const float* __restrict__ l2, const float* __restrict__ l3) {
    int t = threadIdx.x; // 32 threads
    float a = l0[t]*l1[t] + l0[t+32]*l1[t+32];
    float b = l2[t]*l3[t] + l2[t+32]*l3[t+32];
    #pragma unroll
    for (int o = 16; o >= 1; o >>= 1) {
        a += __shfl_xor_sync(0xffffffffu, a, o);
        b += __shfl_xor_sync(0xffffffffu, b, o);
    }
    if (t == 0) g_lambda = (-expf(a) + LAMBDA_INIT) + (-expf(b) + LAMBDA_INIT);
}

// ---------------------------------------------------------------------------
// Generic SGEMM: C[M,N] = A[M,K] @ B[K,N], all row-major.
// 128x128 block tile, BK=8, 256 threads, 8x8 register tile per thread.
// M%128==0, N%128==0, K%8==0 assumed (true for all 6 calls here).
// ---------------------------------------------------------------------------
__global__ __launch_bounds__(256) void sgemm128(const float* __restrict__ A,
                                                const float* __restrict__ B,
                                                float* __restrict__ C,
                                                int M, int N, int K) {
    __shared__ float As[8][132];   // transposed: As[k][m], padded
    __shared__ float Bs[8][132];   // Bs[k][n], padded

    int tid = threadIdx.x;
    int tx = tid & 15;             // n-dir thread coord
    int ty = tid >> 4;             // m-dir thread coord
    int bx = blockIdx.x;           // n tile
    int by = blockIdx.y;           // m tile

    const float* Ab = A + (size_t)(by * 128) * K;
    const float* Bb = B + bx * 128;

    int a_row = tid >> 1;          // 0..127
    int a_col = (tid & 1) * 4;     // 0 or 4
    int b_row = tid >> 5;          // 0..7
    int b_col = (tid & 31) * 4;    // 0..124

    float acc[8][8];
    #pragma unroll
    for (int i = 0; i < 8; i++)
        #pragma unroll
        for (int j = 0; j < 8; j++) acc[i][j] = 0.f;

    for (int k0 = 0; k0 < K; k0 += 8) {
        float4 av = *(const float4*)(Ab + (size_t)a_row * K + k0 + a_col);
        float4 bv = *(const float4*)(Bb + (size_t)(k0 + b_row) * N + b_col);
        __syncthreads();
        As[a_col+0][a_row] = av.x;
        As[a_col+1][a_row] = av.y;
        As[a_col+2][a_row] = av.z;
        As[a_col+3][a_row] = av.w;
        *(float4*)&Bs[b_row][b_col] = bv;
        __syncthreads();
        #pragma unroll
        for (int kk = 0; kk < 8; kk++) {
            float ar[8], br[8];
            *(float4*)(ar)     = *(const float4*)&As[kk][ty*8];
            *(float4*)(ar + 4) = *(const float4*)&As[kk][ty*8 + 4];
            *(float4*)(br)     = *(const float4*)&Bs[kk][tx*8];
            *(float4*)(br + 4) = *(const float4*)&Bs[kk][tx*8 + 4];
            #pragma unroll
            for (int i = 0; i < 8; i++)
                #pragma unroll
                for (int j = 0; j < 8; j++)
                    acc[i][j] += ar[i] * br[j];
        }
    }

    #pragma unroll
    for (int i = 0; i < 8; i++) {
        int row = by * 128 + ty * 8 + i;
        float* Cr = C + (size_t)row * N + bx * 128 + tx * 8;
        *(float4*)(Cr)     = make_float4(acc[i][0], acc[i][1], acc[i][2], acc[i][3]);
        *(float4*)(Cr + 4) = make_float4(acc[i][4], acc[i][5], acc[i][6], acc[i][7]);
    }
}

// ---------------------------------------------------------------------------
// Differential flash attention + per-head LayerNorm.
// Grid: (S/64 q-tiles, B*H). Block: 256 threads = 16(tx, k/dh dir) x 16(ty, q dir),
// each thread owns a 4x4 microtile. Two softmax streams with independent online
// stats; K and P smem buffers reused sequentially per stream (80KB dyn smem).
// ---------------------------------------------------------------------------
#define ATTN_SMEM_FLOATS (8192 + 4096 + 4096 + 4096)
#define ATTN_SMEM_BYTES  (ATTN_SMEM_FLOATS * 4)

__global__ __launch_bounds__(256) void attn_kernel(
        const float* __restrict__ q0b, const float* __restrict__ q1b,
        const float* __restrict__ k0b, const float* __restrict__ k1b,
        const float* __restrict__ vb,
        const float* __restrict__ ln_w, const float* __restrict__ ln_b,
        float* __restrict__ attn) {
    extern __shared__ float sm[];
    float* sQt = sm;           // [2][64 dh][64 q]  (transposed)
    float* sKt = sm + 8192;    // [64 dh][64 k]     (transposed, per-stream reuse)
    float* sV  = sm + 12288;   // [64 k][64 dh]
    float* sP  = sm + 16384;   // [64 q][64 k]      (per-stream reuse)

    int qt = gridDim.x - 1 - blockIdx.x;   // heavy tiles first
    int bh = blockIdx.y;
    int b = bh >> 4, h = bh & 15;

    int tid = threadIdx.x;
    int tx = tid & 15;
    int ty = tid >> 4;

    const float scale = 0.125f;                       // 1/sqrt(64)
    const float slope = exp2f(-0.5f * (float)(h + 1)); // ALiBi slope
    const size_t base = (size_t)b * SEQ * DMODEL + (size_t)h * DHEAD;

    // --- load Q0/Q1 tiles, transposed ---
    {
        int qrow = tid >> 2;            // 0..63
        int dh0  = (tid & 3) * 16;      // 0,16,32,48
        size_t g = base + (size_t)(qt * 64 + qrow) * DMODEL + dh0;
        #pragma unroll
        for (int st = 0; st < 2; st++) {
            const float* src = (st == 0) ? q0b : q1b;
            float* dst = sQt + st * 4096;
            #pragma unroll
            for (int c = 0; c < 16; c += 4) {
                float4 v4 = *(const float4*)(src + g + c);
                dst[(dh0 + c + 0) * 64 + qrow] = v4.x;
                dst[(dh0 + c + 1) * 64 + qrow] = v4.y;
                dst[(dh0 + c + 2) * 64 + qrow] = v4.z;
                dst[(dh0 + c + 3) * 64 + qrow] = v4.w;
            }
        }
    }

    float acc0[4][4], acc1[4][4];
    float m0[4], m1[4], l0s[4], l1s[4];
    #pragma unroll
    for (int i = 0; i < 4; i++) {
        m0[i] = -INFINITY; m1[i] = -INFINITY; l0s[i] = 0.f; l1s[i] = 0.f;
        #pragma unroll
        for (int j = 0; j < 4; j++) { acc0[i][j] = 0.f; acc1[i][j] = 0.f; }
    }

    const int qglob = qt * 64 + ty * 4;

    for (int kt = 0; kt <= qt; kt++) {
        __syncthreads();  // prior iteration's smem reads complete
        // load V tile (stream-independent)
        {
            int krow = tid >> 2;
            int dh0  = (tid & 3) * 16;
            const float* src = vb + base + (size_t)(kt * 64 + krow) * DMODEL + dh0;
            #pragma unroll
            for (int c = 0; c < 16; c += 4)
                *(float4*)(sV + krow * 64 + dh0 + c) = *(const float4*)(src + c);
        }

        const int kglob = kt * 64 + tx * 4;

        #pragma unroll
        for (int st = 0; st < 2; st++) {
            const float* kb = (st == 0) ? k0b : k1b;
            float (*acc)[4] = (st == 0) ? acc0 : acc1;
            float* m = (st == 0) ? m0 : m1;
            float* l = (st == 0) ? l0s : l1s;

            // load K tile transposed
            {
                int krow = tid >> 2;
                int dh0  = (tid & 3) * 16;
                const float* src = kb + base + (size_t)(kt * 64 + krow) * DMODEL + dh0;
                #pragma unroll
                for (int c = 0; c < 16; c += 4) {
                    float4 v4 = *(const float4*)(src + c);
                    sKt[(dh0 + c + 0) * 64 + krow] = v4.x;
                    sKt[(dh0 + c + 1) * 64 + krow] = v4.y;
                    sKt[(dh0 + c + 2) * 64 + krow] = v4.z;
                    sKt[(dh0 + c + 3) * 64 + krow] = v4.w;
                }
            }
            __syncthreads();  // sKt ready; also guarantees prior sP readers done

            // scores (4x4 per thread), QK^T over DH=64
            float sc[4][4];
            #pragma unroll
            for (int i = 0; i < 4; i++)
                #pragma unroll
                for (int j = 0; j < 4; j++) sc[i][j] = 0.f;
            {
                const float* Qp = sQt + st * 4096 + ty * 4;
                const float* Kp = sKt + tx * 4;
                #pragma unroll 16
                for (int dh = 0; dh < 64; dh++) {
                    float4 qv = *(const float4*)(Qp + dh * 64);
                    float4 kv = *(const float4*)(Kp + dh * 64);
                    float qa[4] = {qv.x, qv.y, qv.z, qv.w};
                    float ka[4] = {kv.x, kv.y, kv.z, kv.w};
                    #pragma unroll
                    for (int i = 0; i < 4; i++)
                        #pragma unroll
                        for (int j = 0; j < 4; j++)
                            sc[i][j] += qa[i] * ka[j];
                }
            }

            // bias + causal mask + row max
            float rm[4];
            #pragma unroll
            for (int i = 0; i < 4; i++) {
                float mx = -INFINITY;
                #pragma unroll
                for (int j = 0; j < 4; j++) {
                    int qq = qglob + i, kk = kglob + j;
                    float s = sc[i][j] * scale - slope * (float)(qq - kk);
                    if (kk > qq) s = -INFINITY;
                    sc[i][j] = s;
                    mx = fmaxf(mx, s);
                }
                #pragma unroll
                for (int o = 8; o >= 1; o >>= 1)
                    mx = fmaxf(mx, __shfl_xor_sync(0xffffffffu, mx, o));
                rm[i] = mx;
            }

            // online softmax update + P
            float p[4][4];
            #pragma unroll
            for (int i = 0; i < 4; i++) {
                float mn = fmaxf(m[i], rm[i]);
                float corr = __expf(m[i] - mn);   // exp(-inf)=0 on first tile
                m[i] = mn;
                float rs = 0.f;
                #pragma unroll
                for (int j = 0; j < 4; j++) {
                    float pv = __expf(sc[i][j] - mn);
                    p[i][j] = pv;
                    rs += pv;
                }
                #pragma unroll
                for (int o = 8; o >= 1; o >>= 1)
                    rs += __shfl_xor_sync(0xffffffffu, rs, o);
                l[i] = l[i] * corr + rs;
                #pragma unroll
                for (int j = 0; j < 4; j++) acc[i][j] *= corr;
            }
            #pragma unroll
            for (int i = 0; i < 4; i++)
                *(float4*)(sP + (ty * 4 + i) * 64 + tx * 4) =
                    make_float4(p[i][0], p[i][1], p[i][2], p[i][3]);
            __syncthreads();  // sP ready; all sKt readers done

            // PV: acc += P @ V  (reduction over k, tx now indexes dh)
            #pragma unroll 8
            for (int k = 0; k < 64; k++) {
                float4 vv = *(const float4*)(sV + k * 64 + tx * 4);
                #pragma unroll
                for (int i = 0; i < 4; i++) {
                    float pv = sP[(ty * 4 + i) * 64 + k];
                    acc[i][0] += pv * vv.x;
                    acc[i][1] += pv * vv.y;
                    acc[i][2] += pv * vv.z;
                    acc[i][3] += pv * vv.w;
                }
            }
        }
    }

    // --- epilogue: combine streams, per-head LayerNorm over DH, store ---
    float lam = g_lambda;
    float lw[4], lb[4];
    #pragma unroll
    for (int j = 0; j < 4; j++) {
        lw[j] = ln_w[h * DHEAD + tx * 4 + j];
        lb[j] = ln_b[h * DHEAD + tx * 4 + j];
    }
    #pragma unroll
    for (int i = 0; i < 4; i++) {
        float inv0 = 1.0f / l0s[i];
        float inv1 = 1.0f / l1s[i];
        float o[4];
        float s_ = 0.f;
        #pragma unroll
        for (int j = 0; j < 4; j++) {
            o[j] = acc0[i][j] * inv0 - lam * (acc1[i][j] * inv1);
            s_ += o[j];
        }
        #pragma unroll
        for (int off = 8; off >= 1; off >>= 1)
            s_ += __shfl_xor_sync(0xffffffffu, s_, off);
        float mu = s_ * (1.0f / 64.0f);
        float vs = 0.f;
        #pragma unroll
        for (int j = 0; j < 4; j++) { float d = o[j] - mu; vs += d * d; }
        #pragma unroll
        for (int off = 8; off >= 1; off >>= 1)
            vs += __shfl_xor_sync(0xffffffffu, vs, off);
        float r = rsqrtf(vs * (1.0f / 64.0f) + LN_EPS);

        float4 res;
        res.x = (o[0] - mu) * r * lw[0] + lb[0];
        res.y = (o[1] - mu) * r * lw[1] + lb[1];
        res.z = (o[2] - mu) * r * lw[2] + lb[2];
        res.w = (o[3] - mu) * r * lw[3] + lb[3];
        size_t row = (size_t)b * SEQ + (size_t)(qglob + i);
        *(float4*)(attn + row * DMODEL + h * DHEAD + tx * 4) = res;
    }
}

// ---------------------------------------------------------------------------
// Launch
// ---------------------------------------------------------------------------
extern "C" void kernel_launch(void* const* d_in, const int* in_sizes, int n_in,
                              void* d_out, int out_size) {
    const float* inp = (const float*)d_in[0];
    const float* wq0 = (const float*)d_in[1];
    const float* wq1 = (const float*)d_in[2];
    const float* wk0 = (const float*)d_in[3];
    const float* wk1 = (const float*)d_in[4];
    const float* wv  = (const float*)d_in[5];
    const float* wo  = (const float*)d_in[6];
    const float* l0  = (const float*)d_in[7];
    const float* l1  = (const float*)d_in[8];
    const float* l2  = (const float*)d_in[9];
    const float* l3  = (const float*)d_in[10];
    const float* lnw = (const float*)d_in[11];
    const float* lnb = (const float*)d_in[12];
    float* out = (float*)d_out;

    float *q0, *q1, *k0, *k1, *v, *attn;
    cudaGetSymbolAddress((void**)&q0, g_q0);
    cudaGetSymbolAddress((void**)&q1, g_q1);
    cudaGetSymbolAddress((void**)&k0, g_k0);
    cudaGetSymbolAddress((void**)&k1, g_k1);
    cudaGetSymbolAddress((void**)&v,  g_v);
    cudaGetSymbolAddress((void**)&attn, g_attn);

    cudaFuncSetAttribute(attn_kernel, cudaFuncAttributeMaxDynamicSharedMemorySize,
                         ATTN_SMEM_BYTES);

    lambda_kernel<<<1, 32>>>(l0, l1, l2, l3);

    dim3 ggrid(DMODEL / 128, MTOT / 128);   // (8, 32)
    sgemm128<<<ggrid, 256>>>(inp, wq0, q0, MTOT, DMODEL, DMODEL);
    sgemm128<<<ggrid, 256>>>(inp, wq1, q1, MTOT, DMODEL, DMODEL);
    sgemm128<<<ggrid, 256>>>(inp, wk0, k0, MTOT, DMODEL, DMODEL);
    sgemm128<<<ggrid, 256>>>(inp, wk1, k1, MTOT, DMODEL, DMODEL);
    sgemm128<<<ggrid, 256>>>(inp, wv,  v,  MTOT, DMODEL, DMODEL);

    attn_kernel<<<dim3(SEQ / 64, BATCH * NHEAD), 256, ATTN_SMEM_BYTES>>>(
        q0, q1, k0, k1, v, lnw, lnb, attn);

    sgemm128<<<ggrid, 256>>>(attn, wo, out, MTOT, DMODEL, DMODEL);
}

// round 3
// speedup vs baseline: 1.4855x; 1.4855x over previous
#include <cuda_runtime.h>
#include <math.h>
#include <stdint.h>

// Problem constants
#define BATCH 2
#define SEQ   2048
#define DMODEL 1024
#define NHEAD 16
#define DHEAD 64
#define MTOT  (BATCH*SEQ)      // 4096
#define LAMBDA_INIT 0.8f
#define LN_EPS 1e-5f

// ---------------------------------------------------------------------------
// Scratch (no allocation allowed -> __device__ globals)
// ---------------------------------------------------------------------------
__device__ float g_q0[MTOT*DMODEL];
__device__ float g_q1[MTOT*DMODEL];
__device__ float g_k0[MTOT*DMODEL];
__device__ float g_k1[MTOT*DMODEL];
__device__ float g_v [MTOT*DMODEL];
__device__ float g_attn[MTOT*DMODEL];
__device__ float g_lambda;

// ---------------------------------------------------------------------------
// Lambda scalar
// ---------------------------------------------------------------------------
__global__ void lambda_kernel(const float* __restrict__ l0, const float* __restrict__ l1,
                              const float* __restrict__ l2, const float* __restrict__ l3) {
    int t = threadIdx.x; // 32 threads
    float a = l0[t]*l1[t] + l0[t+32]*l1[t+32];
    float b = l2[t]*l3[t] + l2[t+32]*l3[t+32];
    #pragma unroll
    for (int o = 16; o >= 1; o >>= 1) {
        a += __shfl_xor_sync(0xffffffffu, a, o);
        b += __shfl_xor_sync(0xffffffffu, b, o);
    }
    if (t == 0) g_lambda = (-expf(a) + LAMBDA_INIT) + (-expf(b) + LAMBDA_INIT);
}

// ---------------------------------------------------------------------------
// TF32 tensor-core GEMM: C[M,N] = A[M,K] @ B[K,N], row-major.
// 128x128x32 block tile, 256 threads (8 warps as 2m x 4n, 64x32 warp tiles),
// mma.sync.m16n8k8.tf32, cp.async double-buffered smem.
// ---------------------------------------------------------------------------
#define BM 128
#define BN 128
#define BK 32
#define A_LD 36            // padded A row (floats): 144B pitch -> conflict-free ldmatrix
#define B_LD 136           // padded B row (floats): 544B pitch -> conflict-free scalar LDS
#define AS_STAGE (BM*A_LD) // 4608 floats
#define BS_STAGE (BK*B_LD) // 4352 floats
#define GEMM_SMEM_BYTES ((2*(AS_STAGE+BS_STAGE))*4)  // 71680 B

__device__ __forceinline__ uint32_t cvt_tf32(float x) {
    uint32_t r;
    asm("cvt.rna.tf32.f32 %0, %1;" : "=r"(r) : "f"(x));
    return r;
}

__global__ __launch_bounds__(256, 1) void gemm_tf32(const float* __restrict__ A,
                                                    const float* __restrict__ B,
                                                    float* __restrict__ C,
                                                    int M, int N, int K) {
    extern __shared__ float sm[];
    float* As = sm;                 // [2][BM][A_LD]
    float* Bs = sm + 2 * AS_STAGE;  // [2][BK][B_LD]

    int tid  = threadIdx.x;
    int lane = tid & 31;
    int warp = tid >> 5;
    int g    = lane >> 2;           // group id 0..7
    int tig  = lane & 3;            // thread in group 0..3
    int wm   = (warp >> 2) * 64;    // warp m offset: 0 or 64
    int wn   = (warp & 3) * 32;     // warp n offset: 0,32,64,96

    int bx = blockIdx.x, by = blockIdx.y;

    const float* Ag = A + (size_t)(by * BM) * K;
    const float* Bg = B + bx * BN;

    // cp.async coords
    int a_row = tid >> 3;           // 0..31
    int a_col = (tid & 7) * 4;      // float offset, 16B chunks
    int b_row = tid >> 5;           // 0..7
    int b_col = (tid & 31) * 4;

    uint32_t s_as = (uint32_t)__cvta_generic_to_shared(As);
    uint32_t s_bs = (uint32_t)__cvta_generic_to_shared(Bs);

    float acc[4][4][4];
    #pragma unroll
    for (int i = 0; i < 4; i++)
        #pragma unroll
        for (int j = 0; j < 4; j++)
            #pragma unroll
            for (int q = 0; q < 4; q++) acc[i][j][q] = 0.f;

    // ldmatrix lane-dependent base inside an A stage:
    // row = wm + i*16 + (lane&15), col(k) = k8*8 + (lane>>4)*4
    uint32_t a_lane_off = ((uint32_t)((wm + (lane & 15)) * A_LD + (lane >> 4) * 4)) * 4u;

    const int NT = K / BK;

    auto prefetch = [&](int kt, int stage) {
        uint32_t ad = s_as + (uint32_t)stage * AS_STAGE * 4;
        const float* ag = Ag + kt * BK;
        #pragma unroll
        for (int r = 0; r < 4; r++) {
            int row = a_row + r * 32;
            uint32_t dst = ad + (uint32_t)(row * A_LD + a_col) * 4;
            const float* src = ag + (size_t)row * K + a_col;
            asm volatile("cp.async.cg.shared.global [%0], [%1], 16;\n" :: "r"(dst), "l"(src));
        }
        uint32_t bd = s_bs + (uint32_t)stage * BS_STAGE * 4;
        const float* bg = Bg + (size_t)(kt * BK) * N;
        #pragma unroll
        for (int r = 0; r < 4; r++) {
            int row = b_row + r * 8;
            uint32_t dst = bd + (uint32_t)(row * B_LD + b_col) * 4;
            const float* src = bg + (size_t)row * N + b_col;
            asm volatile("cp.async.cg.shared.global [%0], [%1], 16;\n" :: "r"(dst), "l"(src));
        }
        asm volatile("cp.async.commit_group;\n");
    };

    prefetch(0, 0);

    for (int kt = 0; kt < NT; kt++) {
        int stage = kt & 1;
        if (kt + 1 < NT) {
            prefetch(kt + 1, stage ^ 1);
            asm volatile("cp.async.wait_group 1;\n");
        } else {
            asm volatile("cp.async.wait_group 0;\n");
        }
        __syncthreads();

        uint32_t a_base = s_as + (uint32_t)stage * AS_STAGE * 4 + a_lane_off;
        const float* bsp = Bs + stage * BS_STAGE;

        #pragma unroll
        for (int k8 = 0; k8 < BK / 8; k8++) {
            uint32_t arg[4][4];
            #pragma unroll
            for (int i = 0; i < 4; i++) {
                uint32_t addr = a_base + (uint32_t)(i * 16 * A_LD + k8 * 8) * 4;
                asm volatile("ldmatrix.sync.aligned.m8n8.x4.shared.b16 {%0,%1,%2,%3}, [%4];\n"
                             : "=r"(arg[i][0]), "=r"(arg[i][1]), "=r"(arg[i][2]), "=r"(arg[i][3])
                             : "r"(addr));
            }
            uint32_t brg[4][2];
            #pragma unroll
            for (int j = 0; j < 4; j++) {
                float b0 = bsp[(k8 * 8 + tig)     * B_LD + wn + j * 8 + g];
                float b1 = bsp[(k8 * 8 + tig + 4) * B_LD + wn + j * 8 + g];
                brg[j][0] = cvt_tf32(b0);
                brg[j][1] = cvt_tf32(b1);
            }
            #pragma unroll
            for (int i = 0; i < 4; i++)
                #pragma unroll
                for (int q = 0; q < 4; q++)
                    arg[i][q] = cvt_tf32(__uint_as_float(arg[i][q]));

            #pragma unroll
            for (int i = 0; i < 4; i++)
                #pragma unroll
                for (int j = 0; j < 4; j++)
                    asm volatile(
                        "mma.sync.aligned.m16n8k8.row.col.f32.tf32.tf32.f32 "
                        "{%0,%1,%2,%3}, {%4,%5,%6,%7}, {%8,%9}, {%0,%1,%2,%3};\n"
                        : "+f"(acc[i][j][0]), "+f"(acc[i][j][1]),
                          "+f"(acc[i][j][2]), "+f"(acc[i][j][3])
                        : "r"(arg[i][0]), "r"(arg[i][1]), "r"(arg[i][2]), "r"(arg[i][3]),
                          "r"(brg[j][0]), "r"(brg[j][1]));
        }
        __syncthreads();
    }

    // epilogue: C fragment layout c0=(g,2t) c1=(g,2t+1) c2=(g+8,2t) c3=(g+8,2t+1)
    #pragma unroll
    for (int i = 0; i < 4; i++) {
        int row = by * BM + wm + i * 16 + g;
        #pragma unroll
        for (int j = 0; j < 4; j++) {
            int col = bx * BN + wn + j * 8 + 2 * tig;
            *(float2*)(C + (size_t)row * N + col)       = make_float2(acc[i][j][0], acc[i][j][1]);
            *(float2*)(C + (size_t)(row + 8) * N + col) = make_float2(acc[i][j][2], acc[i][j][3]);
        }
    }
}

// ---------------------------------------------------------------------------
// Differential flash attention + per-head LayerNorm (unchanged from R2 pass).
// ---------------------------------------------------------------------------
#define ATTN_SMEM_FLOATS (8192 + 4096 + 4096 + 4096)
#define ATTN_SMEM_BYTES  (ATTN_SMEM_FLOATS * 4)

__global__ __launch_bounds__(256) void attn_kernel(
        const float* __restrict__ q0b, const float* __restrict__ q1b,
        const float* __restrict__ k0b, const float* __restrict__ k1b,
        const float* __restrict__ vb,
        const float* __restrict__ ln_w, const float* __restrict__ ln_b,
        float* __restrict__ attn) {
    extern __shared__ float sm[];
    float* sQt = sm;           // [2][64 dh][64 q]  (transposed)
    float* sKt = sm + 8192;    // [64 dh][64 k]     (transposed, per-stream reuse)
    float* sV  = sm + 12288;   // [64 k][64 dh]
    float* sP  = sm + 16384;   // [64 q][64 k]      (per-stream reuse)

    int qt = gridDim.x - 1 - blockIdx.x;   // heavy tiles first
    int bh = blockIdx.y;
    int b = bh >> 4, h = bh & 15;

    int tid = threadIdx.x;
    int tx = tid & 15;
    int ty = tid >> 4;

    const float scale = 0.125f;                       // 1/sqrt(64)
    const float slope = exp2f(-0.5f * (float)(h + 1)); // ALiBi slope
    const size_t base = (size_t)b * SEQ * DMODEL + (size_t)h * DHEAD;

    // --- load Q0/Q1 tiles, transposed ---
    {
        int qrow = tid >> 2;            // 0..63
        int dh0  = (tid & 3) * 16;      // 0,16,32,48
        size_t gofs = base + (size_t)(qt * 64 + qrow) * DMODEL + dh0;
        #pragma unroll
        for (int st = 0; st < 2; st++) {
            const float* src = (st == 0) ? q0b : q1b;
            float* dst = sQt + st * 4096;
            #pragma unroll
            for (int c = 0; c < 16; c += 4) {
                float4 v4 = *(const float4*)(src + gofs + c);
                dst[(dh0 + c + 0) * 64 + qrow] = v4.x;
                dst[(dh0 + c + 1) * 64 + qrow] = v4.y;
                dst[(dh0 + c + 2) * 64 + qrow] = v4.z;
                dst[(dh0 + c + 3) * 64 + qrow] = v4.w;
            }
        }
    }

    float acc0[4][4], acc1[4][4];
    float m0[4], m1[4], l0s[4], l1s[4];
    #pragma unroll
    for (int i = 0; i < 4; i++) {
        m0[i] = -INFINITY; m1[i] = -INFINITY; l0s[i] = 0.f; l1s[i] = 0.f;
        #pragma unroll
        for (int j = 0; j < 4; j++) { acc0[i][j] = 0.f; acc1[i][j] = 0.f; }
    }

    const int qglob = qt * 64 + ty * 4;

    for (int kt = 0; kt <= qt; kt++) {
        __syncthreads();  // prior iteration's smem reads complete
        // load V tile (stream-independent)
        {
            int krow = tid >> 2;
            int dh0  = (tid & 3) * 16;
            const float* src = vb + base + (size_t)(kt * 64 + krow) * DMODEL + dh0;
            #pragma unroll
            for (int c = 0; c < 16; c += 4)
                *(float4*)(sV + krow * 64 + dh0 + c) = *(const float4*)(src + c);
        }

        const int kglob = kt * 64 + tx * 4;

        #pragma unroll
        for (int st = 0; st < 2; st++) {
            const float* kb = (st == 0) ? k0b : k1b;
            float (*acc)[4] = (st == 0) ? acc0 : acc1;
            float* m = (st == 0) ? m0 : m1;
            float* l = (st == 0) ? l0s : l1s;

            // load K tile transposed
            {
                int krow = tid >> 2;
                int dh0  = (tid & 3) * 16;
                const float* src = kb + base + (size_t)(kt * 64 + krow) * DMODEL + dh0;
                #pragma unroll
                for (int c = 0; c < 16; c += 4) {
                    float4 v4 = *(const float4*)(src + c);
                    sKt[(dh0 + c + 0) * 64 + krow] = v4.x;
                    sKt[(dh0 + c + 1) * 64 + krow] = v4.y;
                    sKt[(dh0 + c + 2) * 64 + krow] = v4.z;
                    sKt[(dh0 + c + 3) * 64 + krow] = v4.w;
                }
            }
            __syncthreads();  // sKt ready; also guarantees prior sP readers done

            // scores (4x4 per thread), QK^T over DH=64
            float sc[4][4];
            #pragma unroll
            for (int i = 0; i < 4; i++)
                #pragma unroll
                for (int j = 0; j < 4; j++) sc[i][j] = 0.f;
            {
                const float* Qp = sQt + st * 4096 + ty * 4;
                const float* Kp = sKt + tx * 4;
                #pragma unroll 16
                for (int dh = 0; dh < 64; dh++) {
                    float4 qv = *(const float4*)(Qp + dh * 64);
                    float4 kv = *(const float4*)(Kp + dh * 64);
                    float qa[4] = {qv.x, qv.y, qv.z, qv.w};
                    float ka[4] = {kv.x, kv.y, kv.z, kv.w};
                    #pragma unroll
                    for (int i = 0; i < 4; i++)
                        #pragma unroll
                        for (int j = 0; j < 4; j++)
                            sc[i][j] += qa[i] * ka[j];
                }
            }

            // bias + causal mask + row max
            float rm[4];
            #pragma unroll
            for (int i = 0; i < 4; i++) {
                float mx = -INFINITY;
                #pragma unroll
                for (int j = 0; j < 4; j++) {
                    int qq = qglob + i, kk = kglob + j;
                    float s = sc[i][j] * scale - slope * (float)(qq - kk);
                    if (kk > qq) s = -INFINITY;
                    sc[i][j] = s;
                    mx = fmaxf(mx, s);
                }
                #pragma unroll
                for (int o = 8; o >= 1; o >>= 1)
                    mx = fmaxf(mx, __shfl_xor_sync(0xffffffffu, mx, o));
                rm[i] = mx;
            }

            // online softmax update + P
            float p[4][4];
            #pragma unroll
            for (int i = 0; i < 4; i++) {
                float mn = fmaxf(m[i], rm[i]);
                float corr = __expf(m[i] - mn);   // exp(-inf)=0 on first tile
                m[i] = mn;
                float rs = 0.f;
                #pragma unroll
                for (int j = 0; j < 4; j++) {
                    float pv = __expf(sc[i][j] - mn);
                    p[i][j] = pv;
                    rs += pv;
                }
                #pragma unroll
                for (int o = 8; o >= 1; o >>= 1)
                    rs += __shfl_xor_sync(0xffffffffu, rs, o);
                l[i] = l[i] * corr + rs;
                #pragma unroll
                for (int j = 0; j < 4; j++) acc[i][j] *= corr;
            }
            #pragma unroll
            for (int i = 0; i < 4; i++)
                *(float4*)(sP + (ty * 4 + i) * 64 + tx * 4) =
                    make_float4(p[i][0], p[i][1], p[i][2], p[i][3]);
            __syncthreads();  // sP ready; all sKt readers done

            // PV: acc += P @ V  (reduction over k, tx now indexes dh)
            #pragma unroll 8
            for (int k = 0; k < 64; k++) {
                float4 vv = *(const float4*)(sV + k * 64 + tx * 4);
                #pragma unroll
                for (int i = 0; i < 4; i++) {
                    float pv = sP[(ty * 4 + i) * 64 + k];
                    acc[i][0] += pv * vv.x;
                    acc[i][1] += pv * vv.y;
                    acc[i][2] += pv * vv.z;
                    acc[i][3] += pv * vv.w;
                }
            }
        }
    }

    // --- epilogue: combine streams, per-head LayerNorm over DH, store ---
    float lam = g_lambda;
    float lw[4], lb[4];
    #pragma unroll
    for (int j = 0; j < 4; j++) {
        lw[j] = ln_w[h * DHEAD + tx * 4 + j];
        lb[j] = ln_b[h * DHEAD + tx * 4 + j];
    }
    #pragma unroll
    for (int i = 0; i < 4; i++) {
        float inv0 = 1.0f / l0s[i];
        float inv1 = 1.0f / l1s[i];
        float o[4];
        float s_ = 0.f;
        #pragma unroll
        for (int j = 0; j < 4; j++) {
            o[j] = acc0[i][j] * inv0 - lam * (acc1[i][j] * inv1);
            s_ += o[j];
        }
        #pragma unroll
        for (int off = 8; off >= 1; off >>= 1)
            s_ += __shfl_xor_sync(0xffffffffu, s_, off);
        float mu = s_ * (1.0f / 64.0f);
        float vs = 0.f;
        #pragma unroll
        for (int j = 0; j < 4; j++) { float d = o[j] - mu; vs += d * d; }
        #pragma unroll
        for (int off = 8; off >= 1; off >>= 1)
            vs += __shfl_xor_sync(0xffffffffu, vs, off);
        float r = rsqrtf(vs * (1.0f / 64.0f) + LN_EPS);

        float4 res;
        res.x = (o[0] - mu) * r * lw[0] + lb[0];
        res.y = (o[1] - mu) * r * lw[1] + lb[1];
        res.z = (o[2] - mu) * r * lw[2] + lb[2];
        res.w = (o[3] - mu) * r * lw[3] + lb[3];
        size_t row = (size_t)b * SEQ + (size_t)(qglob + i);
        *(float4*)(attn + row * DMODEL + h * DHEAD + tx * 4) = res;
    }
}

// ---------------------------------------------------------------------------
// Launch
// ---------------------------------------------------------------------------
extern "C" void kernel_launch(void* const* d_in, const int* in_sizes, int n_in,
                              void* d_out, int out_size) {
    const float* inp = (const float*)d_in[0];
    const float* wq0 = (const float*)d_in[1];
    const float* wq1 = (const float*)d_in[2];
    const float* wk0 = (const float*)d_in[3];
    const float* wk1 = (const float*)d_in[4];
    const float* wv  = (const float*)d_in[5];
    const float* wo  = (const float*)d_in[6];
    const float* l0  = (const float*)d_in[7];
    const float* l1  = (const float*)d_in[8];
    const float* l2  = (const float*)d_in[9];
    const float* l3  = (const float*)d_in[10];
    const float* lnw = (const float*)d_in[11];
    const float* lnb = (const float*)d_in[12];
    float* out = (float*)d_out;

    float *q0, *q1, *k0, *k1, *v, *attn;
    cudaGetSymbolAddress((void**)&q0, g_q0);
    cudaGetSymbolAddress((void**)&q1, g_q1);
    cudaGetSymbolAddress((void**)&k0, g_k0);
    cudaGetSymbolAddress((void**)&k1, g_k1);
    cudaGetSymbolAddress((void**)&v,  g_v);
    cudaGetSymbolAddress((void**)&attn, g_attn);

    cudaFuncSetAttribute(gemm_tf32, cudaFuncAttributeMaxDynamicSharedMemorySize,
                         GEMM_SMEM_BYTES);
    cudaFuncSetAttribute(attn_kernel, cudaFuncAttributeMaxDynamicSharedMemorySize,
                         ATTN_SMEM_BYTES);

    lambda_kernel<<<1, 32>>>(l0, l1, l2, l3);

    dim3 ggrid(DMODEL / 128, MTOT / 128);   // (8, 32)
    gemm_tf32<<<ggrid, 256, GEMM_SMEM_BYTES>>>(inp, wq0, q0, MTOT, DMODEL, DMODEL);
    gemm_tf32<<<ggrid, 256, GEMM_SMEM_BYTES>>>(inp, wq1, q1, MTOT, DMODEL, DMODEL);
    gemm_tf32<<<ggrid, 256, GEMM_SMEM_BYTES>>>(inp, wk0, k0, MTOT, DMODEL, DMODEL);
    gemm_tf32<<<ggrid, 256, GEMM_SMEM_BYTES>>>(inp, wk1, k1, MTOT, DMODEL, DMODEL);
    gemm_tf32<<<ggrid, 256, GEMM_SMEM_BYTES>>>(inp, wv,  v,  MTOT, DMODEL, DMODEL);

    attn_kernel<<<dim3(SEQ / 64, BATCH * NHEAD), 256, ATTN_SMEM_BYTES>>>(
        q0, q1, k0, k1, v, lnw, lnb, attn);

    gemm_tf32<<<ggrid, 256, GEMM_SMEM_BYTES>>>(attn, wo, out, MTOT, DMODEL, DMODEL);
}

// round 4
// speedup vs baseline: 2.2208x; 1.4950x over previous
#include <cuda_runtime.h>
#include <math.h>
#include <stdint.h>

// Problem constants
#define BATCH 2
#define SEQ   2048
#define DMODEL 1024
#define NHEAD 16
#define DHEAD 64
#define MTOT  (BATCH*SEQ)      // 4096
#define LAMBDA_INIT 0.8f
#define LN_EPS 1e-5f

// ---------------------------------------------------------------------------
// Scratch
// ---------------------------------------------------------------------------
__device__ float g_q0[MTOT*DMODEL];
__device__ float g_q1[MTOT*DMODEL];
__device__ float g_k0[MTOT*DMODEL];
__device__ float g_k1[MTOT*DMODEL];
__device__ float g_v [MTOT*DMODEL];
__device__ float g_attn[MTOT*DMODEL];
__device__ float g_lambda;

__device__ __forceinline__ uint32_t cvt_tf32(float x) {
    uint32_t r;
    asm("cvt.rna.tf32.f32 %0, %1;" : "=r"(r) : "f"(x));
    return r;
}
__device__ __forceinline__ float tf32f(float x) {
    return __uint_as_float(cvt_tf32(x));
}

// ---------------------------------------------------------------------------
// Lambda scalar
// ---------------------------------------------------------------------------
__global__ void lambda_kernel(const float* __restrict__ l0, const float* __restrict__ l1,
                              const float* __restrict__ l2, const float* __restrict__ l3) {
    int t = threadIdx.x; // 32 threads
    float a = l0[t]*l1[t] + l0[t+32]*l1[t+32];
    float b = l2[t]*l3[t] + l2[t+32]*l3[t+32];
    #pragma unroll
    for (int o = 16; o >= 1; o >>= 1) {
        a += __shfl_xor_sync(0xffffffffu, a, o);
        b += __shfl_xor_sync(0xffffffffu, b, o);
    }
    if (t == 0) g_lambda = (-expf(a) + LAMBDA_INIT) + (-expf(b) + LAMBDA_INIT);
}

// ---------------------------------------------------------------------------
// TF32 tensor-core GEMM (unchanged from R3 pass: 83us/launch)
// ---------------------------------------------------------------------------
#define BM 128
#define BN 128
#define BK 32
#define A_LD 36
#define B_LD 136
#define AS_STAGE (BM*A_LD)
#define BS_STAGE (BK*B_LD)
#define GEMM_SMEM_BYTES ((2*(AS_STAGE+BS_STAGE))*4)

__global__ __launch_bounds__(256, 1) void gemm_tf32(const float* __restrict__ A,
                                                    const float* __restrict__ B,
                                                    float* __restrict__ C,
                                                    int M, int N, int K) {
    extern __shared__ float sm[];
    float* As = sm;
    float* Bs = sm + 2 * AS_STAGE;

    int tid  = threadIdx.x;
    int lane = tid & 31;
    int warp = tid >> 5;
    int g    = lane >> 2;
    int tig  = lane & 3;
    int wm   = (warp >> 2) * 64;
    int wn   = (warp & 3) * 32;

    int bx = blockIdx.x, by = blockIdx.y;

    const float* Ag = A + (size_t)(by * BM) * K;
    const float* Bg = B + bx * BN;

    int a_row = tid >> 3;
    int a_col = (tid & 7) * 4;
    int b_row = tid >> 5;
    int b_col = (tid & 31) * 4;

    uint32_t s_as = (uint32_t)__cvta_generic_to_shared(As);
    uint32_t s_bs = (uint32_t)__cvta_generic_to_shared(Bs);

    float acc[4][4][4];
    #pragma unroll
    for (int i = 0; i < 4; i++)
        #pragma unroll
        for (int j = 0; j < 4; j++)
            #pragma unroll
            for (int q = 0; q < 4; q++) acc[i][j][q] = 0.f;

    uint32_t a_lane_off = ((uint32_t)((wm + (lane & 15)) * A_LD + (lane >> 4) * 4)) * 4u;

    const int NT = K / BK;

    auto prefetch = [&](int kt, int stage) {
        uint32_t ad = s_as + (uint32_t)stage * AS_STAGE * 4;
        const float* ag = Ag + kt * BK;
        #pragma unroll
        for (int r = 0; r < 4; r++) {
            int row = a_row + r * 32;
            uint32_t dst = ad + (uint32_t)(row * A_LD + a_col) * 4;
            const float* src = ag + (size_t)row * K + a_col;
            asm volatile("cp.async.cg.shared.global [%0], [%1], 16;\n" :: "r"(dst), "l"(src));
        }
        uint32_t bd = s_bs + (uint32_t)stage * BS_STAGE * 4;
        const float* bg = Bg + (size_t)(kt * BK) * N;
        #pragma unroll
        for (int r = 0; r < 4; r++) {
            int row = b_row + r * 8;
            uint32_t dst = bd + (uint32_t)(row * B_LD + b_col) * 4;
            const float* src = bg + (size_t)row * N + b_col;
            asm volatile("cp.async.cg.shared.global [%0], [%1], 16;\n" :: "r"(dst), "l"(src));
        }
        asm volatile("cp.async.commit_group;\n");
    };

    prefetch(0, 0);

    for (int kt = 0; kt < NT; kt++) {
        int stage = kt & 1;
        if (kt + 1 < NT) {
            prefetch(kt + 1, stage ^ 1);
            asm volatile("cp.async.wait_group 1;\n");
        } else {
            asm volatile("cp.async.wait_group 0;\n");
        }
        __syncthreads();

        uint32_t a_base = s_as + (uint32_t)stage * AS_STAGE * 4 + a_lane_off;
        const float* bsp = Bs + stage * BS_STAGE;

        #pragma unroll
        for (int k8 = 0; k8 < BK / 8; k8++) {
            uint32_t arg[4][4];
            #pragma unroll
            for (int i = 0; i < 4; i++) {
                uint32_t addr = a_base + (uint32_t)(i * 16 * A_LD + k8 * 8) * 4;
                asm volatile("ldmatrix.sync.aligned.m8n8.x4.shared.b16 {%0,%1,%2,%3}, [%4];\n"
                             : "=r"(arg[i][0]), "=r"(arg[i][1]), "=r"(arg[i][2]), "=r"(arg[i][3])
                             : "r"(addr));
            }
            uint32_t brg[4][2];
            #pragma unroll
            for (int j = 0; j < 4; j++) {
                float b0 = bsp[(k8 * 8 + tig)     * B_LD + wn + j * 8 + g];
                float b1 = bsp[(k8 * 8 + tig + 4) * B_LD + wn + j * 8 + g];
                brg[j][0] = cvt_tf32(b0);
                brg[j][1] = cvt_tf32(b1);
            }
            #pragma unroll
            for (int i = 0; i < 4; i++)
                #pragma unroll
                for (int q = 0; q < 4; q++)
                    arg[i][q] = cvt_tf32(__uint_as_float(arg[i][q]));

            #pragma unroll
            for (int i = 0; i < 4; i++)
                #pragma unroll
                for (int j = 0; j < 4; j++)
                    asm volatile(
                        "mma.sync.aligned.m16n8k8.row.col.f32.tf32.tf32.f32 "
                        "{%0,%1,%2,%3}, {%4,%5,%6,%7}, {%8,%9}, {%0,%1,%2,%3};\n"
                        : "+f"(acc[i][j][0]), "+f"(acc[i][j][1]),
                          "+f"(acc[i][j][2]), "+f"(acc[i][j][3])
                        : "r"(arg[i][0]), "r"(arg[i][1]), "r"(arg[i][2]), "r"(arg[i][3]),
                          "r"(brg[j][0]), "r"(brg[j][1]));
        }
        __syncthreads();
    }

    #pragma unroll
    for (int i = 0; i < 4; i++) {
        int row = by * BM + wm + i * 16 + g;
        #pragma unroll
        for (int j = 0; j < 4; j++) {
            int col = bx * BN + wn + j * 8 + 2 * tig;
            *(float2*)(C + (size_t)row * N + col)       = make_float2(acc[i][j][0], acc[i][j][1]);
            *(float2*)(C + (size_t)(row + 8) * N + col) = make_float2(acc[i][j][2], acc[i][j][3]);
        }
    }
}

// ---------------------------------------------------------------------------
// Tensor-core differential flash attention + per-head LayerNorm.
// 128 threads = 4 warps; warp w owns q rows [w*16, w*16+16).
// QK and PV via mma.m16n8k8.tf32. P round-trips through smem (tf32 bits),
// re-read with ldmatrix float-quadrant trick (same scheme as gemm A).
// ---------------------------------------------------------------------------
#define QLD 68   // 68 % 32 = 4 banks shift -> same ldmatrix geometry as A_LD=36
#define PLD 68
#define KLD 72   // 72 % 32 = 8 -> scalar B-frag LDS conflict-free (8*tig+g)
#define VLD 72
#define SQ_OFF 0
#define SK_OFF (2*64*QLD)            // 8704
#define SV_OFF (SK_OFF + 64*KLD)     // 13312
#define SP_OFF (SV_OFF + 64*VLD)     // 17920
#define ATTN2_SMEM_FLOATS (SP_OFF + 64*PLD)   // 22272
#define ATTN2_SMEM_BYTES (ATTN2_SMEM_FLOATS*4)

__global__ __launch_bounds__(128) void attn_tc_kernel(
        const float* __restrict__ q0b, const float* __restrict__ q1b,
        const float* __restrict__ k0b, const float* __restrict__ k1b,
        const float* __restrict__ vb,
        const float* __restrict__ ln_w, const float* __restrict__ ln_b,
        float* __restrict__ attn) {
    extern __shared__ float sm[];
    float* sQ = sm + SQ_OFF;   // [2][64][QLD] tf32 bits
    float* sK = sm + SK_OFF;   // [64 dh][KLD(kv)] tf32 bits, per-stream reuse
    float* sV = sm + SV_OFF;   // [64 kv][VLD(dh)] tf32 bits
    float* sP = sm + SP_OFF;   // [64 q][PLD(kv)] tf32 bits, per-stream reuse

    int qt = gridDim.x - 1 - blockIdx.x;   // heavy tiles first
    int bh = blockIdx.y;
    int b = bh >> 4, h = bh & 15;

    int tid = threadIdx.x;
    int lane = tid & 31;
    int w = tid >> 5;
    int g = lane >> 2;
    int tig = lane & 3;

    const float scale = 0.125f;
    const float slope = exp2f(-0.5f * (float)(h + 1));
    const size_t base = (size_t)b * SEQ * DMODEL + (size_t)h * DHEAD;

    // --- load Q (both streams), row-major, pre-cvt tf32 ---
    {
        int row = tid >> 1;             // 0..63
        int c0  = (tid & 1) * 32;
        size_t gofs = base + (size_t)(qt * 64 + row) * DMODEL + c0;
        #pragma unroll
        for (int st = 0; st < 2; st++) {
            const float* src = (st == 0) ? q0b : q1b;
            float* dst = sQ + st * 64 * QLD + row * QLD + c0;
            #pragma unroll
            for (int c = 0; c < 32; c += 4) {
                float4 v4 = *(const float4*)(src + gofs + c);
                dst[c + 0] = tf32f(v4.x);
                dst[c + 1] = tf32f(v4.y);
                dst[c + 2] = tf32f(v4.z);
                dst[c + 3] = tf32f(v4.w);
            }
        }
    }

    // PV accumulators: [stream][j(dh/8)][4], rows g (regs 0,1) and g+8 (regs 2,3)
    float oacc[2][8][4];
    #pragma unroll
    for (int st = 0; st < 2; st++)
        #pragma unroll
        for (int j = 0; j < 8; j++)
            #pragma unroll
            for (int q = 0; q < 4; q++) oacc[st][j][q] = 0.f;
    float mrow[2][2], lrow[2][2];
    #pragma unroll
    for (int st = 0; st < 2; st++)
        #pragma unroll
        for (int hh = 0; hh < 2; hh++) { mrow[st][hh] = -INFINITY; lrow[st][hh] = 0.f; }

    uint32_t s_q = (uint32_t)__cvta_generic_to_shared(sQ);
    uint32_t s_p = (uint32_t)__cvta_generic_to_shared(sP);
    uint32_t qa_lane = ((uint32_t)((w * 16 + (lane & 15)) * QLD + (lane >> 4) * 4)) * 4u;
    uint32_t pa_lane = s_p + ((uint32_t)((w * 16 + (lane & 15)) * PLD + (lane >> 4) * 4)) * 4u;

    const int qrow0 = qt * 64 + w * 16;        // warp's global q base
    const int qq0 = qrow0 + g;                 // row for half 0 (half 1: +8)

    for (int kt = 0; kt <= qt; kt++) {
        // load V tile (stream-independent), pre-cvt
        {
            int kv = tid >> 1;
            int c0 = (tid & 1) * 32;
            const float* gp = vb + base + (size_t)(kt * 64 + kv) * DMODEL + c0;
            float* dst = sV + kv * VLD + c0;
            #pragma unroll
            for (int c = 0; c < 32; c += 4) {
                float4 v4 = *(const float4*)(gp + c);
                dst[c + 0] = tf32f(v4.x);
                dst[c + 1] = tf32f(v4.y);
                dst[c + 2] = tf32f(v4.z);
                dst[c + 3] = tf32f(v4.w);
            }
        }

        #pragma unroll
        for (int st = 0; st < 2; st++) {
            // load K tile transposed [dh][kv], pre-cvt
            {
                int kv = tid >> 1;
                int c0 = (tid & 1) * 32;
                const float* gp = ((st == 0) ? k0b : k1b) + base
                                  + (size_t)(kt * 64 + kv) * DMODEL + c0;
                #pragma unroll
                for (int c = 0; c < 32; c += 4) {
                    float4 v4 = *(const float4*)(gp + c);
                    sK[(c0 + c + 0) * KLD + kv] = tf32f(v4.x);
                    sK[(c0 + c + 1) * KLD + kv] = tf32f(v4.y);
                    sK[(c0 + c + 2) * KLD + kv] = tf32f(v4.z);
                    sK[(c0 + c + 3) * KLD + kv] = tf32f(v4.w);
                }
            }
            __syncthreads();   // sK (and sV, sQ on first pass) ready

            // ---- QK: scores [16 q rows x 64 kv] per warp ----
            float sc[8][4];
            #pragma unroll
            for (int j = 0; j < 8; j++)
                #pragma unroll
                for (int q = 0; q < 4; q++) sc[j][q] = 0.f;

            uint32_t qa_base = s_q + (uint32_t)(st * 64 * QLD) * 4u + qa_lane;
            #pragma unroll
            for (int k8 = 0; k8 < 8; k8++) {
                uint32_t a0, a1, a2, a3;
                uint32_t addr = qa_base + (uint32_t)(k8 * 8) * 4u;
                asm volatile("ldmatrix.sync.aligned.m8n8.x4.shared.b16 {%0,%1,%2,%3}, [%4];\n"
                             : "=r"(a0), "=r"(a1), "=r"(a2), "=r"(a3) : "r"(addr));
                const float* kp = sK + (k8 * 8 + tig) * KLD;
                #pragma unroll
                for (int j = 0; j < 8; j++) {
                    uint32_t b0 = __float_as_uint(kp[j * 8 + g]);
                    uint32_t b1 = __float_as_uint(kp[4 * KLD + j * 8 + g]);
                    asm volatile(
                        "mma.sync.aligned.m16n8k8.row.col.f32.tf32.tf32.f32 "
                        "{%0,%1,%2,%3}, {%4,%5,%6,%7}, {%8,%9}, {%0,%1,%2,%3};\n"
                        : "+f"(sc[j][0]), "+f"(sc[j][1]), "+f"(sc[j][2]), "+f"(sc[j][3])
                        : "r"(a0), "r"(a1), "r"(a2), "r"(a3), "r"(b0), "r"(b1));
                }
            }

            // ---- softmax (online), rows g and g+8 ----
            #pragma unroll
            for (int hh = 0; hh < 2; hh++) {
                int qq = qq0 + hh * 8;
                float mx = -INFINITY;
                #pragma unroll
                for (int j = 0; j < 8; j++) {
                    #pragma unroll
                    for (int e = 0; e < 2; e++) {
                        int kk = kt * 64 + j * 8 + 2 * tig + e;
                        float s = sc[j][hh * 2 + e] * scale - slope * (float)(qq - kk);
                        if (kk > qq) s = -INFINITY;
                        sc[j][hh * 2 + e] = s;
                        mx = fmaxf(mx, s);
                    }
                }
                mx = fmaxf(mx, __shfl_xor_sync(0xffffffffu, mx, 1));
                mx = fmaxf(mx, __shfl_xor_sync(0xffffffffu, mx, 2));
                float mn = fmaxf(mrow[st][hh], mx);
                float corr = __expf(mrow[st][hh] - mn);
                mrow[st][hh] = mn;
                float rs = 0.f;
                #pragma unroll
                for (int j = 0; j < 8; j++) {
                    #pragma unroll
                    for (int e = 0; e < 2; e++) {
                        float pv = __expf(sc[j][hh * 2 + e] - mn);
                        sc[j][hh * 2 + e] = pv;
                        rs += pv;
                    }
                }
                rs += __shfl_xor_sync(0xffffffffu, rs, 1);
                rs += __shfl_xor_sync(0xffffffffu, rs, 2);
                lrow[st][hh] = lrow[st][hh] * corr + rs;
                #pragma unroll
                for (int j = 0; j < 8; j++) {
                    oacc[st][j][hh * 2 + 0] *= corr;
                    oacc[st][j][hh * 2 + 1] *= corr;
                }
            }

            // ---- write P (tf32 bits) to own-warp rows of sP ----
            #pragma unroll
            for (int hh = 0; hh < 2; hh++) {
                float* pr = sP + (w * 16 + g + hh * 8) * PLD;
                #pragma unroll
                for (int j = 0; j < 8; j++) {
                    float2 pv = make_float2(tf32f(sc[j][hh * 2 + 0]), tf32f(sc[j][hh * 2 + 1]));
                    *(float2*)(pr + j * 8 + 2 * tig) = pv;
                }
            }
            __syncwarp();  // sP rows are warp-private: warp-level visibility suffices

            // ---- PV: oacc += P @ V ----
            #pragma unroll
            for (int k8 = 0; k8 < 8; k8++) {
                uint32_t a0, a1, a2, a3;
                uint32_t addr = pa_lane + (uint32_t)(k8 * 8) * 4u;
                asm volatile("ldmatrix.sync.aligned.m8n8.x4.shared.b16 {%0,%1,%2,%3}, [%4];\n"
                             : "=r"(a0), "=r"(a1), "=r"(a2), "=r"(a3) : "r"(addr));
                const float* vp = sV + (k8 * 8 + tig) * VLD;
                #pragma unroll
                for (int j = 0; j < 8; j++) {
                    uint32_t b0 = __float_as_uint(vp[j * 8 + g]);
                    uint32_t b1 = __float_as_uint(vp[4 * VLD + j * 8 + g]);
                    asm volatile(
                        "mma.sync.aligned.m16n8k8.row.col.f32.tf32.tf32.f32 "
                        "{%0,%1,%2,%3}, {%4,%5,%6,%7}, {%8,%9}, {%0,%1,%2,%3};\n"
                        : "+f"(oacc[st][j][0]), "+f"(oacc[st][j][1]),
                          "+f"(oacc[st][j][2]), "+f"(oacc[st][j][3])
                        : "r"(a0), "r"(a1), "r"(a2), "r"(a3), "r"(b0), "r"(b1));
                }
            }
            __syncthreads();  // all reads of sK/sV done before next overwrite
        }
    }

    // --- epilogue: combine streams, per-head LayerNorm over DH, store ---
    float lam = g_lambda;
    #pragma unroll
    for (int hh = 0; hh < 2; hh++) {
        float inv0 = 1.0f / lrow[0][hh];
        float inv1 = 1.0f / lrow[1][hh];
        float o[8][2];
        float s_ = 0.f;
        #pragma unroll
        for (int j = 0; j < 8; j++) {
            #pragma unroll
            for (int e = 0; e < 2; e++) {
                float val = oacc[0][j][hh * 2 + e] * inv0
                          - lam * (oacc[1][j][hh * 2 + e] * inv1);
                o[j][e] = val;
                s_ += val;
            }
        }
        s_ += __shfl_xor_sync(0xffffffffu, s_, 1);
        s_ += __shfl_xor_sync(0xffffffffu, s_, 2);
        float mu = s_ * (1.0f / 64.0f);
        float vs = 0.f;
        #pragma unroll
        for (int j = 0; j < 8; j++) {
            #pragma unroll
            for (int e = 0; e < 2; e++) { float d = o[j][e] - mu; vs += d * d; }
        }
        vs += __shfl_xor_sync(0xffffffffu, vs, 1);
        vs += __shfl_xor_sync(0xffffffffu, vs, 2);
        float r = rsqrtf(vs * (1.0f / 64.0f) + LN_EPS);

        size_t row = (size_t)b * SEQ + (size_t)(qrow0 + g + hh * 8);
        #pragma unroll
        for (int j = 0; j < 8; j++) {
            int col = h * DHEAD + j * 8 + 2 * tig;
            float wv0 = ln_w[h * DHEAD + j * 8 + 2 * tig];
            float wv1 = ln_w[h * DHEAD + j * 8 + 2 * tig + 1];
            float bv0 = ln_b[h * DHEAD + j * 8 + 2 * tig];
            float bv1 = ln_b[h * DHEAD + j * 8 + 2 * tig + 1];
            float2 res = make_float2((o[j][0] - mu) * r * wv0 + bv0,
                                     (o[j][1] - mu) * r * wv1 + bv1);
            *(float2*)(attn + row * DMODEL + col) = res;
        }
    }
}

// ---------------------------------------------------------------------------
// Launch
// ---------------------------------------------------------------------------
extern "C" void kernel_launch(void* const* d_in, const int* in_sizes, int n_in,
                              void* d_out, int out_size) {
    const float* inp = (const float*)d_in[0];
    const float* wq0 = (const float*)d_in[1];
    const float* wq1 = (const float*)d_in[2];
    const float* wk0 = (const float*)d_in[3];
    const float* wk1 = (const float*)d_in[4];
    const float* wv  = (const float*)d_in[5];
    const float* wo  = (const float*)d_in[6];
    const float* l0  = (const float*)d_in[7];
    const float* l1  = (const float*)d_in[8];
    const float* l2  = (const float*)d_in[9];
    const float* l3  = (const float*)d_in[10];
    const float* lnw = (const float*)d_in[11];
    const float* lnb = (const float*)d_in[12];
    float* out = (float*)d_out;

    float *q0, *q1, *k0, *k1, *v, *attn;
    cudaGetSymbolAddress((void**)&q0, g_q0);
    cudaGetSymbolAddress((void**)&q1, g_q1);
    cudaGetSymbolAddress((void**)&k0, g_k0);
    cudaGetSymbolAddress((void**)&k1, g_k1);
    cudaGetSymbolAddress((void**)&v,  g_v);
    cudaGetSymbolAddress((void**)&attn, g_attn);

    cudaFuncSetAttribute(gemm_tf32, cudaFuncAttributeMaxDynamicSharedMemorySize,
                         GEMM_SMEM_BYTES);
    cudaFuncSetAttribute(attn_tc_kernel, cudaFuncAttributeMaxDynamicSharedMemorySize,
                         ATTN2_SMEM_BYTES);

    lambda_kernel<<<1, 32>>>(l0, l1, l2, l3);

    dim3 ggrid(DMODEL / 128, MTOT / 128);   // (8, 32)
    gemm_tf32<<<ggrid, 256, GEMM_SMEM_BYTES>>>(inp, wq0, q0, MTOT, DMODEL, DMODEL);
    gemm_tf32<<<ggrid, 256, GEMM_SMEM_BYTES>>>(inp, wq1, q1, MTOT, DMODEL, DMODEL);
    gemm_tf32<<<ggrid, 256, GEMM_SMEM_BYTES>>>(inp, wk0, k0, MTOT, DMODEL, DMODEL);
    gemm_tf32<<<ggrid, 256, GEMM_SMEM_BYTES>>>(inp, wk1, k1, MTOT, DMODEL, DMODEL);
    gemm_tf32<<<ggrid, 256, GEMM_SMEM_BYTES>>>(inp, wv,  v,  MTOT, DMODEL, DMODEL);

    attn_tc_kernel<<<dim3(SEQ / 64, BATCH * NHEAD), 128, ATTN2_SMEM_BYTES>>>(
        q0, q1, k0, k1, v, lnw, lnb, attn);

    gemm_tf32<<<ggrid, 256, GEMM_SMEM_BYTES>>>(attn, wo, out, MTOT, DMODEL, DMODEL);
}